// round 15
// baseline (speedup 1.0000x reference)
#include <cuda_runtime.h>
#include <cuda_fp16.h>
#include <math.h>
#include <stdint.h>

#define SEQ   2048
#define BATCH 2
#define EMB   1024
#define NH    16
#define HD    64
#define QKVN  (3*EMB)       // 3072
#define ROWS  (BATCH*SEQ)   // 4096

// ---------------- device scratch ----------------
__device__ __half g_x[ROWS*EMB];            // x fp16
__device__ __half g_a[ROWS*EMB];            // attn-out fp16
__device__ __half g_Wq[EMB*QKVN];           // Wqkv^T fp16 [N,K]
__device__ __half g_Wo[EMB*EMB];            // Wout^T fp16 [N,K]
// attention operands per (b,h), all [bh][s][d]
__device__ __half g_q[ROWS*EMB];
__device__ __half g_k[ROWS*EMB];
__device__ __half g_v[ROWS*EMB];
__device__ float2 g_rot[SEQ*32];            // (cos, sin) per (s, dim-pair)

// ---------------- helpers ----------------
__device__ __forceinline__ uint32_t smem_u32(const void* p) {
    uint32_t a;
    asm("{ .reg .u64 t; cvta.to.shared.u64 t, %1; cvt.u32.u64 %0, t; }" : "=r"(a) : "l"(p));
    return a;
}
__device__ __forceinline__ void ldsm_x4(uint32_t* r, uint32_t addr) {
    asm volatile("ldmatrix.sync.aligned.m8n8.x4.shared.b16 {%0,%1,%2,%3}, [%4];"
                 : "=r"(r[0]), "=r"(r[1]), "=r"(r[2]), "=r"(r[3]) : "r"(addr));
}
__device__ __forceinline__ void ldsm_x4_t(uint32_t* r, uint32_t addr) {
    asm volatile("ldmatrix.sync.aligned.m8n8.x4.trans.shared.b16 {%0,%1,%2,%3}, [%4];"
                 : "=r"(r[0]), "=r"(r[1]), "=r"(r[2]), "=r"(r[3]) : "r"(addr));
}
__device__ __forceinline__ void mma_f16(float* d, const uint32_t* a, const uint32_t* b) {
    asm volatile("mma.sync.aligned.m16n8k16.row.col.f32.f16.f16.f32 "
        "{%0,%1,%2,%3}, {%4,%5,%6,%7}, {%8,%9}, {%0,%1,%2,%3};"
        : "+f"(d[0]), "+f"(d[1]), "+f"(d[2]), "+f"(d[3])
        : "r"(a[0]), "r"(a[1]), "r"(a[2]), "r"(a[3]), "r"(b[0]), "r"(b[1]));
}
__device__ __forceinline__ uint32_t pack_hf(float a, float b) {
    __half2 t = __floats2half2_rn(a, b);
    return *(uint32_t*)&t;
}
__device__ __forceinline__ void cpa16(uint32_t dst, const void* src) {
    asm volatile("cp.async.cg.shared.global [%0], [%1], 16;" :: "r"(dst), "l"(src));
}

// ---------------- conversion kernels ----------------
__global__ __launch_bounds__(256) void conv4_kernel(const float* __restrict__ in,
                                                    __half* __restrict__ outh) {
    int i = blockIdx.x * 256 + threadIdx.x;
    float4 v = ((const float4*)in)[i];
    ((uint32_t*)outh)[2*i]   = pack_hf(v.x, v.y);
    ((uint32_t*)outh)[2*i+1] = pack_hf(v.z, v.w);
}

// in [K][N] fp32 -> out [N][K] fp16 (tiled transpose)
__global__ __launch_bounds__(256) void convT_kernel(const float* __restrict__ in,
                                                    __half* __restrict__ outT,
                                                    int K, int N) {
    __shared__ float t[32][33];
    int n0 = blockIdx.x * 32, k0 = blockIdx.y * 32;
    int tx = threadIdx.x, ty = threadIdx.y;   // block (32,8)
#pragma unroll
    for (int j = 0; j < 4; j++)
        t[ty + j*8][tx] = in[(size_t)(k0 + ty + j*8) * N + n0 + tx];
    __syncthreads();
#pragma unroll
    for (int j = 0; j < 4; j++) {
        int nl = ty + j*8;
        outT[(size_t)(n0 + nl) * K + k0 + tx] = __float2half(t[tx][nl]);
    }
}

// ---------------- RoPE cos/sin table ----------------
__global__ __launch_bounds__(256) void rot_kernel() {
    int idx = blockIdx.x * 256 + threadIdx.x;   // SEQ*32
    int s = idx >> 5, i = idx & 31;
    float freq = powf(10000.f, -(float)(2*i) / 64.f);
    float sv, cv;
    sincosf((float)s * freq, &sv, &cv);
    g_rot[idx] = make_float2(cv, sv);
}

// ---------------- fp16 GEMM core: 256x128 tile, BK=32, double-buffered ----------------
#define LDSB    80
#define A_T     20480                  // 256 rows * 80
#define B_T     10240                  // 128 rows * 80
#define STAGE_B (A_T + B_T)            // 30720 : A|B
#define MM_SMEM (2*STAGE_B)            // 61440

template<int NR>
__device__ __forceinline__ void cpa_rows(uint32_t dst, const __half* __restrict__ g,
                                         int ld, int row0, int k0, int tid) {
#pragma unroll
    for (int l = 0; l < NR/64; l++) {
        int idx = tid + l * 256;
        int r   = idx >> 2;
        int seg = idx & 3;
        cpa16(dst + r*LDSB + seg*16, g + (size_t)(row0 + r) * ld + k0 + seg*8);
    }
}

// mainloop producing acc[4][8][4]; epilogue left to the caller
__device__ __forceinline__ void gemm_mainloop(const __half* __restrict__ A,
                                              const __half* __restrict__ B,
                                              int K, int m0, int n0,
                                              float acc[4][8][4]) {
    extern __shared__ __align__(128) char smem[];
    const uint32_t sb = smem_u32(smem);
    const int tid  = threadIdx.x;
    const int wid  = tid >> 5;
    const int lane = tid & 31;
    const int wm   = wid >> 1;
    const int wn   = wid & 1;

#pragma unroll
    for (int mf = 0; mf < 4; mf++)
#pragma unroll
        for (int nf = 0; nf < 8; nf++)
#pragma unroll
            for (int c = 0; c < 4; c++) acc[mf][nf][c] = 0.f;

    const uint32_t aoff = (lane & 15) * LDSB + (lane >> 4) * 16;
    const uint32_t boff = ((lane & 7) + ((lane >> 4) << 3)) * LDSB + (((lane >> 3) & 1) * 16);

    const int NIT = K / 32;

    cpa_rows<256>(sb,         A, K, m0, 0, tid);
    cpa_rows<128>(sb + A_T,   B, K, n0, 0, tid);
    asm volatile("cp.async.commit_group;" ::: "memory");

    for (int it = 0; it < NIT; it++) {
        if (it + 1 < NIT) {
            const uint32_t nb = sb + ((it + 1) & 1) * STAGE_B;
            const int k2 = (it + 1) * 32;
            cpa_rows<256>(nb,       A, K, m0, k2, tid);
            cpa_rows<128>(nb + A_T, B, K, n0, k2, tid);
            asm volatile("cp.async.commit_group;" ::: "memory");
            asm volatile("cp.async.wait_group 1;" ::: "memory");
        } else {
            asm volatile("cp.async.wait_group 0;" ::: "memory");
        }
        __syncthreads();

        const uint32_t cbs = sb + (it & 1) * STAGE_B;
#pragma unroll
        for (int ks = 0; ks < 2; ks++) {
            const uint32_t kb = ks * 32;
            uint32_t ar[4][4];
#pragma unroll
            for (int mf = 0; mf < 4; mf++)
                ldsm_x4(ar[mf], cbs + (wm*64 + mf*16) * LDSB + aoff + kb);
#pragma unroll
            for (int nc = 0; nc < 4; nc++) {
                uint32_t br[4];
                ldsm_x4(br, cbs + A_T + (wn*64 + nc*16) * LDSB + boff + kb);
#pragma unroll
                for (int mf = 0; mf < 4; mf++) {
                    mma_f16(acc[mf][nc*2],   ar[mf], br);
                    mma_f16(acc[mf][nc*2+1], ar[mf], br + 2);
                }
            }
        }
        __syncthreads();
    }
}

// qkv GEMM: fused epilogue does rope + scale + fp16 + [bh][s][d] layout
__global__ __launch_bounds__(256) void qkv_mma_kernel() {
    float acc[4][8][4];
    const int m0 = blockIdx.y * 256;
    const int n0 = blockIdx.x * 128;
    gemm_mainloop(g_x, g_Wq, EMB, m0, n0, acc);

    const int tid  = threadIdx.x;
    const int wid  = tid >> 5;
    const int lane = tid & 31;
    const int wm   = wid >> 1;
    const int wn   = wid & 1;

    const int cw    = n0 + wn * 64;        // warp column base: one (which, head)
    const int which = cw >> 10;            // 0:q 1:k 2:v (warp-uniform)
    const int h     = (cw >> 6) & 15;
    __half* dst = (which == 0) ? g_q : ((which == 1) ? g_k : g_v);
    const float sc = (which == 0) ? 0.125f : 1.f;

    const int r0 = m0 + wm * 64 + (lane >> 2);
    const int d0 = (lane & 3) * 2;
#pragma unroll
    for (int mf = 0; mf < 4; mf++) {
        const int r = r0 + mf * 16;
        const int b = r >> 11;
        const int s = r & (SEQ - 1);       // r..r+8 never cross a 2048 boundary
        const size_t base = ((size_t)(b * NH + h)) * SEQ;
#pragma unroll
        for (int nf = 0; nf < 8; nf++) {
            const float* a = acc[mf][nf];
            const int d = d0 + nf * 8;
            if (which < 2) {
                float2 cs0 = g_rot[s * 32 + (d >> 1)];
                float2 cs1 = g_rot[(s + 8) * 32 + (d >> 1)];
                float o0 = (a[0] * cs0.x - a[1] * cs0.y) * sc;
                float o1 = (a[0] * cs0.y + a[1] * cs0.x) * sc;
                float o2 = (a[2] * cs1.x - a[3] * cs1.y) * sc;
                float o3 = (a[2] * cs1.y + a[3] * cs1.x) * sc;
                *(uint32_t*)&dst[(base + s)     * HD + d] = pack_hf(o0, o1);
                *(uint32_t*)&dst[(base + s + 8) * HD + d] = pack_hf(o2, o3);
            } else {
                *(uint32_t*)&dst[(base + s)     * HD + d] = pack_hf(a[0], a[1]);
                *(uint32_t*)&dst[(base + s + 8) * HD + d] = pack_hf(a[2], a[3]);
            }
        }
    }
}

// out GEMM: plain fp32 epilogue
__global__ __launch_bounds__(256) void out_mma_kernel(float* __restrict__ out) {
    float acc[4][8][4];
    const int m0 = blockIdx.y * 256;
    const int n0 = blockIdx.x * 128;
    gemm_mainloop(g_a, g_Wo, EMB, m0, n0, acc);

    const int tid  = threadIdx.x;
    const int wid  = tid >> 5;
    const int lane = tid & 31;
    const int wm   = wid >> 1;
    const int wn   = wid & 1;
    const int r0 = m0 + wm * 64 + (lane >> 2);
    const int c0 = n0 + wn * 64 + (lane & 3) * 2;
#pragma unroll
    for (int mf = 0; mf < 4; mf++)
#pragma unroll
        for (int nf = 0; nf < 8; nf++) {
            const float* a = acc[mf][nf];
            const int r = r0 + mf * 16;
            const int c = c0 + nf * 8;
            *(float2*)&out[(size_t)r * EMB + c]       = make_float2(a[0], a[1]);
            *(float2*)&out[(size_t)(r + 8) * EMB + c] = make_float2(a[2], a[3]);
        }
}

// ---------------- fp16 tensor-core flash attention ----------------
// Q 128 rows; K/V 64-row tiles, both [s][d]; V consumed via trans ldmatrix.
#define AQS    144                      // smem row stride bytes
#define SQ_O   0
#define SSTG   18432                    // stages start
#define STG_B  18432                    // K|V per stage
#define SK_O   0
#define SV_O   9216
#define ATT_SMEM (SSTG + 2*STG_B)       // 55296

__device__ __forceinline__ void attn_kv_load(uint32_t sbase, size_t qk, int kt, int tid) {
#pragma unroll
    for (int l = 0; l < 4; l++) {
        int idx = tid + l * 256;        // 0..1023
        int mat = idx >> 9;             // 0:K 1:V (warp-uniform)
        int r   = (idx >> 3) & 63;
        int c   = idx & 7;
        const __half* g = mat ? g_v : g_k;
        uint32_t o = mat ? SV_O : SK_O;
        cpa16(sbase + o + r*AQS + c*16, g + qk + (size_t)(kt*64 + r)*HD + c*8);
    }
}

__global__ __launch_bounds__(256, 2) void attn_mma_kernel() {
    extern __shared__ __align__(128) char sm[];
    const uint32_t sb = smem_u32(sm);
    const int tid  = threadIdx.x;
    const int w    = tid >> 5;
    const int lane = tid & 31;
    const int qt   = 15 - (int)blockIdx.y;      // heavy tiles first
    const int bh   = blockIdx.z;
    const int qbase = qt * 128;
    const size_t qk = (size_t)bh * SEQ * HD;    // q/k/v [s][d] base

    // Q tile via cp.async
#pragma unroll
    for (int l = 0; l < 4; l++) {
        int idx = tid + l * 256;        // 0..1023
        int r   = idx >> 3;             // 0..127
        int c   = idx & 7;
        cpa16(sb + SQ_O + r*AQS + c*16, g_q + qk + (size_t)(qbase + r)*HD + c*8);
    }
    attn_kv_load(sb + SSTG, qk, 0, tid);
    asm volatile("cp.async.commit_group;" ::: "memory");

    const uint32_t aoff = (lane & 15) * AQS + (lane >> 4) * 16;
    const uint32_t boff = ((lane & 7) + ((lane >> 4) << 3)) * AQS + ((lane >> 3) & 1) * 16;
    const uint32_t vloff = aoff;                 // trans-ldmatrix lane offset for V
    const int r0 = qbase + w * 16;

    float o[8][4];
#pragma unroll
    for (int t = 0; t < 8; t++)
#pragma unroll
        for (int c = 0; c < 4; c++) o[t][c] = 0.f;
    float m0r = -1e30f, m1r = -1e30f, l0r = 0.f, l1r = 0.f;

    const int nkt = 2 * qt + 2;
    for (int kt = 0; kt < nkt; kt++) {
        if (kt + 1 < nkt) {
            attn_kv_load(sb + SSTG + ((kt + 1) & 1) * STG_B, qk, kt + 1, tid);
            asm volatile("cp.async.commit_group;" ::: "memory");
            asm volatile("cp.async.wait_group 1;" ::: "memory");
        } else {
            asm volatile("cp.async.wait_group 0;" ::: "memory");
        }
        __syncthreads();

        const uint32_t stg = sb + SSTG + (kt & 1) * STG_B;

        if (kt * 64 <= r0 + 15) {    // tile not fully masked for this warp
            // ---- S = Q K^T ----
            float st[8][4];
#pragma unroll
            for (int t = 0; t < 8; t++)
#pragma unroll
                for (int c = 0; c < 4; c++) st[t][c] = 0.f;

#pragma unroll
            for (int j = 0; j < 4; j++) {
                uint32_t qr[4];
                ldsm_x4(qr, sb + SQ_O + w*16*AQS + aoff + j*32);
#pragma unroll
                for (int nb = 0; nb < 4; nb++) {
                    uint32_t kr[4];
                    ldsm_x4(kr, stg + SK_O + nb*16*AQS + boff + j*32);
                    mma_f16(st[2*nb],   qr, kr);
                    mma_f16(st[2*nb+1], qr, kr + 2);
                }
            }

            // ---- causal mask ----
            const int rq0 = r0 + (lane >> 2);
            if (kt * 64 + 63 > r0) {
#pragma unroll
                for (int t = 0; t < 8; t++) {
                    int c = kt*64 + t*8 + (lane & 3)*2;
                    if (c     > rq0)     st[t][0] = -1e30f;
                    if (c + 1 > rq0)     st[t][1] = -1e30f;
                    if (c     > rq0 + 8) st[t][2] = -1e30f;
                    if (c + 1 > rq0 + 8) st[t][3] = -1e30f;
                }
            }

            // ---- online softmax ----
            float rm0 = -1e30f, rm1 = -1e30f;
#pragma unroll
            for (int t = 0; t < 8; t++) {
                rm0 = fmaxf(rm0, fmaxf(st[t][0], st[t][1]));
                rm1 = fmaxf(rm1, fmaxf(st[t][2], st[t][3]));
            }
            rm0 = fmaxf(rm0, __shfl_xor_sync(0xffffffffu, rm0, 1));
            rm0 = fmaxf(rm0, __shfl_xor_sync(0xffffffffu, rm0, 2));
            rm1 = fmaxf(rm1, __shfl_xor_sync(0xffffffffu, rm1, 1));
            rm1 = fmaxf(rm1, __shfl_xor_sync(0xffffffffu, rm1, 2));
            float mn0 = fmaxf(m0r, rm0), mn1 = fmaxf(m1r, rm1);
            float al0 = __expf(m0r - mn0), al1 = __expf(m1r - mn1);
            float rs0 = 0.f, rs1 = 0.f;
#pragma unroll
            for (int t = 0; t < 8; t++) {
                st[t][0] = __expf(st[t][0] - mn0);
                st[t][1] = __expf(st[t][1] - mn0);
                st[t][2] = __expf(st[t][2] - mn1);
                st[t][3] = __expf(st[t][3] - mn1);
                rs0 += st[t][0] + st[t][1];
                rs1 += st[t][2] + st[t][3];
            }
            rs0 += __shfl_xor_sync(0xffffffffu, rs0, 1);
            rs0 += __shfl_xor_sync(0xffffffffu, rs0, 2);
            rs1 += __shfl_xor_sync(0xffffffffu, rs1, 1);
            rs1 += __shfl_xor_sync(0xffffffffu, rs1, 2);
            l0r = l0r * al0 + rs0;
            l1r = l1r * al1 + rs1;
            m0r = mn0; m1r = mn1;
#pragma unroll
            for (int t = 0; t < 8; t++) {
                o[t][0] *= al0; o[t][1] *= al0;
                o[t][2] *= al1; o[t][3] *= al1;
            }

            // ---- O += P V (V [s][d] via trans ldmatrix) ----
#pragma unroll
            for (int j = 0; j < 4; j++) {
                uint32_t ph[4];
                ph[0] = pack_hf(st[2*j][0],   st[2*j][1]);
                ph[1] = pack_hf(st[2*j][2],   st[2*j][3]);
                ph[2] = pack_hf(st[2*j+1][0], st[2*j+1][1]);
                ph[3] = pack_hf(st[2*j+1][2], st[2*j+1][3]);
#pragma unroll
                for (int db = 0; db < 4; db++) {
                    uint32_t vr[4];
                    ldsm_x4_t(vr, stg + SV_O + j*16*AQS + vloff + db*32);
                    mma_f16(o[2*db],   ph, vr);
                    mma_f16(o[2*db+1], ph, vr + 2);
                }
            }
        }
        __syncthreads();
    }

    // ---- epilogue: normalize, fp16, write g_a ----
    const int b = bh >> 4, h = bh & 15;
    const float inv0 = 1.f / l0r, inv1 = 1.f / l1r;
    const int rq0 = qbase + w*16 + (lane >> 2);
#pragma unroll
    for (int t = 0; t < 8; t++) {
        int col = h * HD + t*8 + (lane & 3) * 2;
        size_t i0 = ((size_t)b*SEQ + rq0)     * EMB + col;
        size_t i1 = ((size_t)b*SEQ + rq0 + 8) * EMB + col;
        *(uint32_t*)&g_a[i0] = pack_hf(o[t][0] * inv0, o[t][1] * inv0);
        *(uint32_t*)&g_a[i1] = pack_hf(o[t][2] * inv1, o[t][3] * inv1);
    }
}

// ---------------- launch ----------------
extern "C" void kernel_launch(void* const* d_in, const int* in_sizes, int n_in,
                              void* d_out, int out_size) {
    const float* x    = (const float*)d_in[0];
    const float* Wqkv = (const float*)d_in[1];
    const float* Wout = (const float*)d_in[2];
    float* out = (float*)d_out;

    cudaFuncSetAttribute(attn_mma_kernel, cudaFuncAttributeMaxDynamicSharedMemorySize, ATT_SMEM);
    cudaFuncSetAttribute(qkv_mma_kernel,  cudaFuncAttributeMaxDynamicSharedMemorySize, MM_SMEM);
    cudaFuncSetAttribute(out_mma_kernel,  cudaFuncAttributeMaxDynamicSharedMemorySize, MM_SMEM);

    __half *p_x, *p_Wq, *p_Wo;
    cudaGetSymbolAddress((void**)&p_x,  g_x);
    cudaGetSymbolAddress((void**)&p_Wq, g_Wq);
    cudaGetSymbolAddress((void**)&p_Wo, g_Wo);

    // rope table (needed by qkv epilogue), input conversions
    rot_kernel<<<(SEQ*32)/256, 256>>>();
    conv4_kernel<<<(ROWS*EMB)/4/256, 256>>>(x, p_x);
    convT_kernel<<<dim3(QKVN/32, EMB/32), dim3(32,8)>>>(Wqkv, p_Wq, EMB, QKVN);
    // QKV projection with fused rope/fp16/layout epilogue
    qkv_mma_kernel<<<dim3(QKVN/128, ROWS/256), 256, MM_SMEM>>>();
    // flash attention
    attn_mma_kernel<<<dim3(1, SEQ/128, BATCH*NH), 256, ATT_SMEM>>>();
    // output projection
    convT_kernel<<<dim3(EMB/32, EMB/32), dim3(32,8)>>>(Wout, p_Wo, EMB, EMB);
    out_mma_kernel<<<dim3(EMB/128, ROWS/256), 256, MM_SMEM>>>(out);
}